// round 16
// baseline (speedup 1.0000x reference)
#include <cuda_runtime.h>
#include <cuda_fp16.h>
#include <cstdint>
#include <cstddef>

#define N_NODES 100000
#define N_EDGES 1600000
#define DIM 128
#define FC_OUT 64

// ---------------- scratch (static __device__, no allocation) ----------------
__device__ __half g_h[(size_t)N_NODES * DIM];    // gather table (fp16)
__device__ __half g_a[(size_t)N_NODES * DIM];    // layer activations (fp16)
__device__ __half g_w1[DIM * DIM];               // transposed fp16 weights
__device__ __half g_w2[DIM * DIM];
__device__ __half g_wfc[FC_OUT * DIM];
__device__ int   g_deg[N_NODES];
__device__ int   g_rowstart[N_NODES];
__device__ int   g_cursor[N_NODES];
__device__ int   g_col[N_EDGES];
__device__ float g_dinv[N_NODES];
__device__ int   g_total;

// ---------------- helpers ----------------
__device__ __forceinline__ uint32_t s2u(const void* p) {
    uint32_t a;
    asm("{ .reg .u64 t; cvta.to.shared.u64 t, %1; cvt.u32.u64 %0, t; }" : "=r"(a) : "l"(p));
    return a;
}
__device__ __forceinline__ void ldsm_x4(uint32_t addr, uint32_t& r0, uint32_t& r1,
                                        uint32_t& r2, uint32_t& r3) {
    asm volatile("ldmatrix.sync.aligned.m8n8.x4.shared.b16 {%0,%1,%2,%3}, [%4];"
                 : "=r"(r0), "=r"(r1), "=r"(r2), "=r"(r3) : "r"(addr));
}
__device__ __forceinline__ void mma_fp16(float* d, const uint32_t* a, const uint32_t* b) {
    asm volatile(
        "mma.sync.aligned.m16n8k16.row.col.f32.f16.f16.f32 "
        "{%0,%1,%2,%3}, {%4,%5,%6,%7}, {%8,%9}, {%0,%1,%2,%3};"
        : "+f"(d[0]), "+f"(d[1]), "+f"(d[2]), "+f"(d[3])
        : "r"(a[0]), "r"(a[1]), "r"(a[2]), "r"(a[3]), "r"(b[0]), "r"(b[1]));
}

// ---------------- weight prep (fp16 transpose) ----------------
__global__ void k_prep_w(const float* __restrict__ W1, const float* __restrict__ W2,
                         const float* __restrict__ Wfc) {
    int i = blockIdx.x * blockDim.x + threadIdx.x;
    if (i < 16384) {
        int n = i >> 7, k = i & 127;
        g_w1[i] = __float2half_rn(W1[k * 128 + n]);
        g_w2[i] = __float2half_rn(W2[k * 128 + n]);
    }
    if (i < 8192) {
        int n = i >> 7, k = i & 127;   // n in [0,64)
        g_wfc[i] = __float2half_rn(Wfc[k * 64 + n]);
    }
}

// ---------------- CSR build ----------------
__global__ void k_hist(const int* __restrict__ dst) {
    int q = blockIdx.x * blockDim.x + threadIdx.x;     // 4 edges/thread
    if (q < N_EDGES / 4) {
        int4 d = ((const int4*)dst)[q];
        atomicAdd(&g_deg[d.x], 1);
        atomicAdd(&g_deg[d.y], 1);
        atomicAdd(&g_deg[d.z], 1);
        atomicAdd(&g_deg[d.w], 1);
    }
}

// one-launch rowstart: block scan + global ticket. Segment placement is
// allocation-order dependent; per-node segment contents / outputs unchanged.
// Also computes dinv and cursor (replaces scan1 + finalize + dinv).
__global__ void k_rowstart() {
    __shared__ int wtot[8];
    __shared__ int wbase[8];
    __shared__ int blockBase;
    int i    = blockIdx.x * 256 + threadIdx.x;
    int lane = threadIdx.x & 31;
    int wid  = threadIdx.x >> 5;

    int d = (i < N_NODES) ? g_deg[i] : 0;
    int incl = d;
#pragma unroll
    for (int off = 1; off < 32; off <<= 1) {
        int t = __shfl_up_sync(0xffffffffu, incl, off);
        if (lane >= off) incl += t;
    }
    if (lane == 31) wtot[wid] = incl;
    __syncthreads();
    if (threadIdx.x == 0) {
        int run = 0;
#pragma unroll
        for (int w = 0; w < 8; w++) { int t = wtot[w]; wbase[w] = run; run += t; }
        blockBase = atomicAdd(&g_total, run);
    }
    __syncthreads();
    if (i < N_NODES) {
        int excl = blockBase + wbase[wid] + incl - d;
        g_rowstart[i] = excl;
        g_cursor[i]   = excl;
        g_dinv[i]     = rsqrtf((float)(d + 1));
    }
}

__global__ void k_scatter(const int* __restrict__ src, const int* __restrict__ dst) {
    int q = blockIdx.x * blockDim.x + threadIdx.x;
    if (q < N_EDGES / 4) {
        int4 d = ((const int4*)dst)[q];
        int4 s = ((const int4*)src)[q];
        g_col[atomicAdd(&g_cursor[d.x], 1)] = s.x;
        g_col[atomicAdd(&g_cursor[d.y], 1)] = s.y;
        g_col[atomicAdd(&g_cursor[d.z], 1)] = s.z;
        g_col[atomicAdd(&g_cursor[d.w], 1)] = s.w;
    }
}

// scale table rows by dinv (applied after GEMM1 which ran without dinv)
__global__ void k_scale(__half* __restrict__ H) {
    int i = blockIdx.x * blockDim.x + threadIdx.x;   // uint2 units (4 halves)
    if (i >= N_NODES * 32) return;
    float di = g_dinv[i >> 5];
    uint2 v = ((uint2*)H)[i];
    float2 fa = __half22float2(*(__half2*)&v.x);
    float2 fb = __half22float2(*(__half2*)&v.y);
    uint2 o;
    *(__half2*)&o.x = __halves2half2(__float2half_rn(fa.x * di), __float2half_rn(fa.y * di));
    *(__half2*)&o.y = __halves2half2(__float2half_rn(fb.x * di), __float2half_rn(fb.y * di));
    ((uint2*)H)[i] = o;
}

#define ROWB 272

// ---------------- mma.sync GEMM (fp16): C[M,N] = A[M,128] @ Bt[N,128]^T -----------
// 128-row M tile, 256 threads, 2 CTAs/SM. B fragments via ldmatrix.x4.
// N==128, SCALE: fp16 table out (*dinv). N==128, !SCALE: raw fp16 out (GEMM1).
// N==64: fp32 + bias (FC).
template <int N, bool F32IN, bool SCALE>
__global__ void __launch_bounds__(256, 2)
k_gemm_mma(const float* __restrict__ Araw, const __half* __restrict__ Ah,
           const __half* __restrict__ Bt,
           const float* __restrict__ bias, void* __restrict__ Cout) {
    extern __shared__ char sm[];
    char* pA = sm;
    char* pB = sm + 128 * ROWB;

    const int tid  = threadIdx.x;
    const int wid  = tid >> 5;
    const int lane = tid & 31;
    const int m0   = blockIdx.x * 128;

    if (F32IN) {
#pragma unroll
        for (int it = 0; it < 16; it++) {
            int idx = tid + it * 256;
            int r = idx >> 5, c4 = idx & 31;
            int m = m0 + r;
            float4 v = make_float4(0.f, 0.f, 0.f, 0.f);
            if (m < N_NODES) v = *(const float4*)(Araw + (size_t)m * 128 + c4 * 4);
            __half2* dh = (__half2*)(pA + r * ROWB + c4 * 8);
            dh[0] = __halves2half2(__float2half_rn(v.x), __float2half_rn(v.y));
            dh[1] = __halves2half2(__float2half_rn(v.z), __float2half_rn(v.w));
        }
    } else {
#pragma unroll
        for (int it = 0; it < 8; it++) {
            int idx = tid + it * 256;
            int r = idx >> 4, c = idx & 15;
            int m = m0 + r;
            uint4 v = make_uint4(0, 0, 0, 0);
            if (m < N_NODES) v = *(const uint4*)(Ah + (size_t)m * 128 + c * 8);
            *(uint4*)(pA + r * ROWB + c * 16) = v;
        }
    }
#pragma unroll
    for (int it = 0; it < N / 16; it++) {
        int idx = tid + it * 256;
        int r = idx >> 4, c = idx & 15;
        *(uint4*)(pB + r * ROWB + c * 16) = *(const uint4*)(Bt + (size_t)r * 128 + c * 8);
    }
    __syncthreads();

    constexpr int WN = (N == 128) ? 64 : 32;
    constexpr int NT = WN / 8;                 // 8 or 4
    const int wm = (wid & 3) * 32;
    const int wn = (wid >> 2) * WN;

    float acc[2][NT][4];
#pragma unroll
    for (int mi = 0; mi < 2; mi++)
#pragma unroll
        for (int ni = 0; ni < NT; ni++)
#pragma unroll
            for (int r = 0; r < 4; r++) acc[mi][ni][r] = 0.f;

    const uint32_t baseA = s2u(pA);
    const uint32_t baseB = s2u(pB);

    const int aRowOff = (lane & 7) + ((lane >> 3) & 1) * 8;
    const int aKByte  = ((lane >> 4) & 1) * 16;
    const int bTileSel = lane >> 4;
    const int bRowOff  = lane & 7;
    const int bKByte   = ((lane >> 3) & 1) * 16;

#pragma unroll
    for (int ks = 0; ks < 8; ks++) {
        const int kb = ks * 32;

        uint32_t a[2][4];
#pragma unroll
        for (int mi = 0; mi < 2; mi++) {
            uint32_t arow = (uint32_t)(wm + mi * 16 + aRowOff);
            ldsm_x4(baseA + arow * ROWB + kb + aKByte, a[mi][0], a[mi][1], a[mi][2], a[mi][3]);
        }
        uint32_t b[NT][2];
#pragma unroll
        for (int ni = 0; ni < NT; ni += 2) {
            uint32_t brow = (uint32_t)(wn + (ni + bTileSel) * 8 + bRowOff);
            ldsm_x4(baseB + brow * ROWB + kb + bKByte,
                    b[ni][0], b[ni][1], b[ni + 1][0], b[ni + 1][1]);
        }
#pragma unroll
        for (int mi = 0; mi < 2; mi++)
#pragma unroll
            for (int ni = 0; ni < NT; ni++)
                mma_fp16(acc[mi][ni], a[mi], b[ni]);
    }

    const int erow = lane >> 2;
    const int ecol = (lane & 3) * 2;
    if (N == 128) {
        __half* C = (__half*)Cout;
#pragma unroll
        for (int mi = 0; mi < 2; mi++) {
            int r0 = m0 + wm + mi * 16 + erow;
            int r1 = r0 + 8;
            float di0 = 1.f, di1 = 1.f;
            if (SCALE) {
                di0 = (r0 < N_NODES) ? g_dinv[r0] : 0.f;
                di1 = (r1 < N_NODES) ? g_dinv[r1] : 0.f;
            }
#pragma unroll
            for (int ni = 0; ni < NT; ni++) {
                int col = wn + ni * 8 + ecol;
                if (r0 < N_NODES) {
                    float v0 = SCALE ? acc[mi][ni][0] * di0 : acc[mi][ni][0];
                    float v1 = SCALE ? acc[mi][ni][1] * di0 : acc[mi][ni][1];
                    *(__half2*)(C + (size_t)r0 * 128 + col) =
                        __halves2half2(__float2half_rn(v0), __float2half_rn(v1));
                }
                if (r1 < N_NODES) {
                    float v2 = SCALE ? acc[mi][ni][2] * di1 : acc[mi][ni][2];
                    float v3 = SCALE ? acc[mi][ni][3] * di1 : acc[mi][ni][3];
                    *(__half2*)(C + (size_t)r1 * 128 + col) =
                        __halves2half2(__float2half_rn(v2), __float2half_rn(v3));
                }
            }
        }
    } else {
        float* C = (float*)Cout;
#pragma unroll
        for (int mi = 0; mi < 2; mi++) {
            int r0 = m0 + wm + mi * 16 + erow;
            int r1 = r0 + 8;
#pragma unroll
            for (int ni = 0; ni < NT; ni++) {
                int col = wn + ni * 8 + ecol;
                float bx = bias[col], by = bias[col + 1];
                if (r0 < N_NODES)
                    *(float2*)(C + (size_t)r0 * N + col) =
                        make_float2(acc[mi][ni][0] + bx, acc[mi][ni][1] + by);
                if (r1 < N_NODES)
                    *(float2*)(C + (size_t)r1 * N + col) =
                        make_float2(acc[mi][ni][2] + bx, acc[mi][ni][3] + by);
            }
        }
    }
}

// ---------------- aggregation: warp per node, pre-scaled fp16 table, MLP=8 ----------
__global__ void k_agg(const __half* __restrict__ H, const float* __restrict__ bias,
                      __half* __restrict__ O) {
    int gw   = (blockIdx.x * blockDim.x + threadIdx.x) >> 5;
    int lane = threadIdx.x & 31;
    if (gw >= N_NODES) return;

    int   start = g_rowstart[gw];
    int   cnt   = g_deg[gw];
    float di    = g_dinv[gw];

    const uint2* H2 = (const uint2*)H;

    float ax, ay, az, aw;
    {
        uint2 v = H2[(size_t)gw * 32 + lane];
        float2 f0 = __half22float2(*(__half2*)&v.x);
        float2 f1 = __half22float2(*(__half2*)&v.y);
        ax = f0.x; ay = f0.y; az = f1.x; aw = f1.y;
    }

    int j = 0;
    for (; j + 8 <= cnt; j += 8) {
        int s[8];
#pragma unroll
        for (int u = 0; u < 8; u++) s[u] = g_col[start + j + u];
        uint2 vv[8];
#pragma unroll
        for (int u = 0; u < 8; u++) vv[u] = H2[(size_t)s[u] * 32 + lane];
#pragma unroll
        for (int u = 0; u < 8; u++) {
            float2 f0 = __half22float2(*(__half2*)&vv[u].x);
            float2 f1 = __half22float2(*(__half2*)&vv[u].y);
            ax += f0.x; ay += f0.y; az += f1.x; aw += f1.y;
        }
    }
    for (; j < cnt; j++) {
        int s = g_col[start + j];
        uint2 v = H2[(size_t)s * 32 + lane];
        float2 f0 = __half22float2(*(__half2*)&v.x);
        float2 f1 = __half22float2(*(__half2*)&v.y);
        ax += f0.x; ay += f0.y; az += f1.x; aw += f1.y;
    }

    float4 b4 = ((const float4*)bias)[lane];
    float ox = fmaxf(fmaf(ax, di, b4.x), 0.f);
    float oy = fmaxf(fmaf(ay, di, b4.y), 0.f);
    float oz = fmaxf(fmaf(az, di, b4.z), 0.f);
    float ow = fmaxf(fmaf(aw, di, b4.w), 0.f);

    __half2* O2 = (__half2*)(O + (size_t)gw * 128);
    O2[lane * 2]     = __halves2half2(__float2half_rn(ox), __float2half_rn(oy));
    O2[lane * 2 + 1] = __halves2half2(__float2half_rn(oz), __float2half_rn(ow));
}

// ---------------- launch ----------------
extern "C" void kernel_launch(void* const* d_in, const int* in_sizes, int n_in,
                              void* d_out, int out_size) {
    const float* x   = (const float*)d_in[0];
    const int*   ei  = (const int*)d_in[1];
    const float* W1  = (const float*)d_in[2];
    const float* b1  = (const float*)d_in[3];
    const float* W2  = (const float*)d_in[4];
    const float* b2  = (const float*)d_in[5];
    const float* Wfc = (const float*)d_in[6];
    const float* bfc = (const float*)d_in[7];
    float*       out = (float*)d_out;

    const int* src = ei;
    const int* dst = ei + N_EDGES;

    __half *hbuf = nullptr, *abuf = nullptr, *w1 = nullptr, *w2 = nullptr, *wfc = nullptr;
    int *degp = nullptr, *totp = nullptr;
    cudaGetSymbolAddress((void**)&hbuf, g_h);
    cudaGetSymbolAddress((void**)&abuf, g_a);
    cudaGetSymbolAddress((void**)&w1,   g_w1);
    cudaGetSymbolAddress((void**)&w2,   g_w2);
    cudaGetSymbolAddress((void**)&wfc,  g_wfc);
    cudaGetSymbolAddress((void**)&degp, g_deg);
    cudaGetSymbolAddress((void**)&totp, g_total);

    static cudaStream_t sB = nullptr;
    static cudaEvent_t  evFork = nullptr, evJoin = nullptr;
    if (!sB) {
        cudaStreamCreateWithFlags(&sB, cudaStreamNonBlocking);
        cudaEventCreateWithFlags(&evFork, cudaEventDisableTiming);
        cudaEventCreateWithFlags(&evJoin, cudaEventDisableTiming);
    }

    const int SMEM128 = (128 + 128) * ROWB;   // 69632
    const int SMEM64  = (128 + 64) * ROWB;    // 52224
    cudaFuncSetAttribute(k_gemm_mma<128, true, false>,
                         cudaFuncAttributeMaxDynamicSharedMemorySize, SMEM128);
    cudaFuncSetAttribute(k_gemm_mma<128, false, true>,
                         cudaFuncAttributeMaxDynamicSharedMemorySize, SMEM128);
    cudaFuncSetAttribute(k_gemm_mma<64, false, false>,
                         cudaFuncAttributeMaxDynamicSharedMemorySize, SMEM64);

    const int nodeBlocks = (N_NODES + 255) / 256;         // 391
    const int quadBlocks = (N_EDGES / 4 + 255) / 256;     // 1563
    const int tcBlocks   = (N_NODES + 127) / 128;         // 782
    const int aggBlocks  = (N_NODES * 32 + 255) / 256;    // 12500

    // fork sB from the capture ROOT so GEMM1 runs concurrent with the whole CSR build
    cudaEventRecord(evFork, 0);
    cudaStreamWaitEvent(sB, evFork, 0);

    // side stream: weight prep -> GEMM1 (unscaled table); independent of CSR
    k_prep_w<<<64, 256, 0, sB>>>(W1, W2, Wfc);
    k_gemm_mma<128, true, false><<<tcBlocks, 256, SMEM128, sB>>>(x, nullptr, w1, nullptr, hbuf);
    cudaEventRecord(evJoin, sB);

    // main stream: CSR build (hist -> rowstart(+dinv+cursor) -> scatter)
    cudaMemsetAsync(degp, 0, N_NODES * sizeof(int), 0);
    cudaMemsetAsync(totp, 0, sizeof(int), 0);
    k_hist<<<quadBlocks, 256>>>(dst);
    k_rowstart<<<nodeBlocks, 256>>>();
    k_scatter<<<quadBlocks, 256>>>(src, dst);

    // join: need GEMM1's table and the CSR
    cudaStreamWaitEvent(0, evJoin, 0);

    // apply dinv to table1, then the serial core (agg owns the chip)
    k_scale<<<(N_NODES * 32 + 255) / 256, 256>>>(hbuf);
    k_agg<<<aggBlocks, 256>>>(hbuf, b1, abuf);
    k_gemm_mma<128, false, true><<<tcBlocks, 256, SMEM128>>>(nullptr, abuf, w2, nullptr, hbuf);
    k_agg<<<aggBlocks, 256>>>(hbuf, b2, abuf);
    k_gemm_mma<64, false, false><<<tcBlocks, 256, SMEM64>>>(nullptr, abuf, wfc, bfc, out);
}

// round 17
// speedup vs baseline: 1.0794x; 1.0794x over previous
#include <cuda_runtime.h>
#include <cuda_fp16.h>
#include <cstdint>
#include <cstddef>

#define N_NODES 100000
#define N_EDGES 1600000
#define DIM 128
#define FC_OUT 64
#define SCAN_BLK 1024
#define N_SCAN_BLKS ((N_NODES + SCAN_BLK - 1) / SCAN_BLK)   // 98

// ---------------- scratch (static __device__, no allocation) ----------------
__device__ __half g_h[(size_t)N_NODES * DIM];    // gather table: h * dinv (fp16)
__device__ __half g_a[(size_t)N_NODES * DIM];    // layer activations (fp16)
__device__ __half g_w1[DIM * DIM];               // transposed fp16 weights
__device__ __half g_w2[DIM * DIM];
__device__ __half g_wfc[FC_OUT * DIM];
__device__ int   g_deg[N_NODES];
__device__ int   g_rowstart[N_NODES];
__device__ int   g_cursor[N_NODES];
__device__ int   g_col[N_EDGES];
__device__ float g_dinv[N_NODES];
__device__ int   g_incl[N_NODES];
__device__ int   g_blk[N_SCAN_BLKS + 1];

// ---------------- helpers ----------------
__device__ __forceinline__ uint32_t s2u(const void* p) {
    uint32_t a;
    asm("{ .reg .u64 t; cvta.to.shared.u64 t, %1; cvt.u32.u64 %0, t; }" : "=r"(a) : "l"(p));
    return a;
}
__device__ __forceinline__ void ldsm_x4(uint32_t addr, uint32_t& r0, uint32_t& r1,
                                        uint32_t& r2, uint32_t& r3) {
    asm volatile("ldmatrix.sync.aligned.m8n8.x4.shared.b16 {%0,%1,%2,%3}, [%4];"
                 : "=r"(r0), "=r"(r1), "=r"(r2), "=r"(r3) : "r"(addr));
}
__device__ __forceinline__ void mma_fp16(float* d, const uint32_t* a, const uint32_t* b) {
    asm volatile(
        "mma.sync.aligned.m16n8k16.row.col.f32.f16.f16.f32 "
        "{%0,%1,%2,%3}, {%4,%5,%6,%7}, {%8,%9}, {%0,%1,%2,%3};"
        : "+f"(d[0]), "+f"(d[1]), "+f"(d[2]), "+f"(d[3])
        : "r"(a[0]), "r"(a[1]), "r"(a[2]), "r"(a[3]), "r"(b[0]), "r"(b[1]));
}

// ---------------- weight prep (fp16 transpose; runs on side stream) ----------------
__global__ void k_prep_w(const float* __restrict__ W1, const float* __restrict__ W2,
                         const float* __restrict__ Wfc) {
    int i = blockIdx.x * blockDim.x + threadIdx.x;
    if (i < 16384) {
        int n = i >> 7, k = i & 127;
        g_w1[i] = __float2half_rn(W1[k * 128 + n]);
        g_w2[i] = __float2half_rn(W2[k * 128 + n]);
    }
    if (i < 8192) {
        int n = i >> 7, k = i & 127;   // n in [0,64)
        g_wfc[i] = __float2half_rn(Wfc[k * 64 + n]);
    }
}

// ---------------- CSR build ----------------
__global__ void k_hist(const int* __restrict__ dst) {
    int e = blockIdx.x * blockDim.x + threadIdx.x;
    if (e < N_EDGES) atomicAdd(&g_deg[dst[e]], 1);
}

__global__ void k_dinv() {
    int i = blockIdx.x * blockDim.x + threadIdx.x;
    if (i < N_NODES) g_dinv[i] = rsqrtf((float)(g_deg[i] + 1));
}

__global__ void k_scan1() {
    __shared__ int s[SCAN_BLK];
    int i = blockIdx.x * SCAN_BLK + threadIdx.x;
    int v = (i < N_NODES) ? g_deg[i] : 0;
    s[threadIdx.x] = v;
    __syncthreads();
    for (int off = 1; off < SCAN_BLK; off <<= 1) {
        int t = (threadIdx.x >= off) ? s[threadIdx.x - off] : 0;
        __syncthreads();
        s[threadIdx.x] += t;
        __syncthreads();
    }
    if (i < N_NODES) g_incl[i] = s[threadIdx.x];
    if (threadIdx.x == SCAN_BLK - 1) g_blk[blockIdx.x] = s[SCAN_BLK - 1];
}

__global__ void k_finalize() {
    __shared__ int s_off;
    if (threadIdx.x == 0) s_off = 0;
    __syncthreads();
    if (threadIdx.x < blockIdx.x) atomicAdd(&s_off, g_blk[threadIdx.x]);
    __syncthreads();
    int i = blockIdx.x * SCAN_BLK + threadIdx.x;
    if (i < N_NODES) {
        int d = g_deg[i];
        int excl = g_incl[i] - d + s_off;
        g_rowstart[i] = excl;
        g_cursor[i]   = excl;
    }
}

__global__ void k_scatter(const int* __restrict__ src, const int* __restrict__ dst) {
    int e = blockIdx.x * blockDim.x + threadIdx.x;
    if (e < N_EDGES) {
        int d = dst[e];
        int p = atomicAdd(&g_cursor[d], 1);
        g_col[p] = src[e];
    }
}

#define ROWB 272

// ---------------- mma.sync GEMM (fp16): C[M,N] = A[M,128] @ Bt[N,128]^T -----------
// 128-row M tile, 256 threads, 2 CTAs/SM. B fragments via ldmatrix.x4 (2 n-tiles/instr).
// N==128: fp16 table out (*dinv). N==64: fp32 + bias.
template <int N, bool F32IN>
__global__ void __launch_bounds__(256, 2)
k_gemm_mma(const float* __restrict__ Araw, const __half* __restrict__ Ah,
           const __half* __restrict__ Bt,
           const float* __restrict__ bias, void* __restrict__ Cout) {
    extern __shared__ char sm[];
    char* pA = sm;
    char* pB = sm + 128 * ROWB;

    const int tid  = threadIdx.x;
    const int wid  = tid >> 5;
    const int lane = tid & 31;
    const int m0   = blockIdx.x * 128;

    if (F32IN) {
#pragma unroll
        for (int it = 0; it < 16; it++) {
            int idx = tid + it * 256;
            int r = idx >> 5, c4 = idx & 31;
            int m = m0 + r;
            float4 v = make_float4(0.f, 0.f, 0.f, 0.f);
            if (m < N_NODES) v = *(const float4*)(Araw + (size_t)m * 128 + c4 * 4);
            __half2* dh = (__half2*)(pA + r * ROWB + c4 * 8);
            dh[0] = __halves2half2(__float2half_rn(v.x), __float2half_rn(v.y));
            dh[1] = __halves2half2(__float2half_rn(v.z), __float2half_rn(v.w));
        }
    } else {
#pragma unroll
        for (int it = 0; it < 8; it++) {
            int idx = tid + it * 256;
            int r = idx >> 4, c = idx & 15;
            int m = m0 + r;
            uint4 v = make_uint4(0, 0, 0, 0);
            if (m < N_NODES) v = *(const uint4*)(Ah + (size_t)m * 128 + c * 8);
            *(uint4*)(pA + r * ROWB + c * 16) = v;
        }
    }
#pragma unroll
    for (int it = 0; it < N / 16; it++) {
        int idx = tid + it * 256;
        int r = idx >> 4, c = idx & 15;
        *(uint4*)(pB + r * ROWB + c * 16) = *(const uint4*)(Bt + (size_t)r * 128 + c * 8);
    }
    __syncthreads();

    constexpr int WN = (N == 128) ? 64 : 32;
    constexpr int NT = WN / 8;                 // 8 or 4
    const int wm = (wid & 3) * 32;
    const int wn = (wid >> 2) * WN;

    float acc[2][NT][4];
#pragma unroll
    for (int mi = 0; mi < 2; mi++)
#pragma unroll
        for (int ni = 0; ni < NT; ni++)
#pragma unroll
            for (int r = 0; r < 4; r++) acc[mi][ni][r] = 0.f;

    const uint32_t baseA = s2u(pA);
    const uint32_t baseB = s2u(pB);

    const int aRowOff = (lane & 7) + ((lane >> 3) & 1) * 8;
    const int aKByte  = ((lane >> 4) & 1) * 16;
    const int bTileSel = lane >> 4;
    const int bRowOff  = lane & 7;
    const int bKByte   = ((lane >> 3) & 1) * 16;

#pragma unroll
    for (int ks = 0; ks < 8; ks++) {
        const int kb = ks * 32;

        uint32_t a[2][4];
#pragma unroll
        for (int mi = 0; mi < 2; mi++) {
            uint32_t arow = (uint32_t)(wm + mi * 16 + aRowOff);
            ldsm_x4(baseA + arow * ROWB + kb + aKByte, a[mi][0], a[mi][1], a[mi][2], a[mi][3]);
        }
        uint32_t b[NT][2];
#pragma unroll
        for (int ni = 0; ni < NT; ni += 2) {
            uint32_t brow = (uint32_t)(wn + (ni + bTileSel) * 8 + bRowOff);
            ldsm_x4(baseB + brow * ROWB + kb + bKByte,
                    b[ni][0], b[ni][1], b[ni + 1][0], b[ni + 1][1]);
        }
#pragma unroll
        for (int mi = 0; mi < 2; mi++)
#pragma unroll
            for (int ni = 0; ni < NT; ni++)
                mma_fp16(acc[mi][ni], a[mi], b[ni]);
    }

    const int erow = lane >> 2;
    const int ecol = (lane & 3) * 2;
    if (N == 128) {
        __half* C = (__half*)Cout;
#pragma unroll
        for (int mi = 0; mi < 2; mi++) {
            int r0 = m0 + wm + mi * 16 + erow;
            int r1 = r0 + 8;
            float di0 = (r0 < N_NODES) ? g_dinv[r0] : 0.f;
            float di1 = (r1 < N_NODES) ? g_dinv[r1] : 0.f;
#pragma unroll
            for (int ni = 0; ni < NT; ni++) {
                int col = wn + ni * 8 + ecol;
                if (r0 < N_NODES)
                    *(__half2*)(C + (size_t)r0 * 128 + col) =
                        __halves2half2(__float2half_rn(acc[mi][ni][0] * di0),
                                       __float2half_rn(acc[mi][ni][1] * di0));
                if (r1 < N_NODES)
                    *(__half2*)(C + (size_t)r1 * 128 + col) =
                        __halves2half2(__float2half_rn(acc[mi][ni][2] * di1),
                                       __float2half_rn(acc[mi][ni][3] * di1));
            }
        }
    } else {
        float* C = (float*)Cout;
#pragma unroll
        for (int mi = 0; mi < 2; mi++) {
            int r0 = m0 + wm + mi * 16 + erow;
            int r1 = r0 + 8;
#pragma unroll
            for (int ni = 0; ni < NT; ni++) {
                int col = wn + ni * 8 + ecol;
                float bx = bias[col], by = bias[col + 1];
                if (r0 < N_NODES)
                    *(float2*)(C + (size_t)r0 * N + col) =
                        make_float2(acc[mi][ni][0] + bx, acc[mi][ni][1] + by);
                if (r1 < N_NODES)
                    *(float2*)(C + (size_t)r1 * N + col) =
                        make_float2(acc[mi][ni][2] + bx, acc[mi][ni][3] + by);
            }
        }
    }
}

// ---------------- aggregation: warp per node, pre-scaled fp16 table, MLP=8 ----------
__global__ void k_agg(const __half* __restrict__ H, const float* __restrict__ bias,
                      __half* __restrict__ O) {
    int gw   = (blockIdx.x * blockDim.x + threadIdx.x) >> 5;
    int lane = threadIdx.x & 31;
    if (gw >= N_NODES) return;

    int   start = g_rowstart[gw];
    int   cnt   = g_deg[gw];
    float di    = g_dinv[gw];

    const uint2* H2 = (const uint2*)H;

    float ax, ay, az, aw;
    {
        uint2 v = H2[(size_t)gw * 32 + lane];
        float2 f0 = __half22float2(*(__half2*)&v.x);
        float2 f1 = __half22float2(*(__half2*)&v.y);
        ax = f0.x; ay = f0.y; az = f1.x; aw = f1.y;
    }

    int j = 0;
    for (; j + 8 <= cnt; j += 8) {
        int s[8];
#pragma unroll
        for (int u = 0; u < 8; u++) s[u] = g_col[start + j + u];
        uint2 vv[8];
#pragma unroll
        for (int u = 0; u < 8; u++) vv[u] = H2[(size_t)s[u] * 32 + lane];
#pragma unroll
        for (int u = 0; u < 8; u++) {
            float2 f0 = __half22float2(*(__half2*)&vv[u].x);
            float2 f1 = __half22float2(*(__half2*)&vv[u].y);
            ax += f0.x; ay += f0.y; az += f1.x; aw += f1.y;
        }
    }
    for (; j < cnt; j++) {
        int s = g_col[start + j];
        uint2 v = H2[(size_t)s * 32 + lane];
        float2 f0 = __half22float2(*(__half2*)&v.x);
        float2 f1 = __half22float2(*(__half2*)&v.y);
        ax += f0.x; ay += f0.y; az += f1.x; aw += f1.y;
    }

    float4 b4 = ((const float4*)bias)[lane];
    float ox = fmaxf(fmaf(ax, di, b4.x), 0.f);
    float oy = fmaxf(fmaf(ay, di, b4.y), 0.f);
    float oz = fmaxf(fmaf(az, di, b4.z), 0.f);
    float ow = fmaxf(fmaf(aw, di, b4.w), 0.f);

    __half2* O2 = (__half2*)(O + (size_t)gw * 128);
    O2[lane * 2]     = __halves2half2(__float2half_rn(ox), __float2half_rn(oy));
    O2[lane * 2 + 1] = __halves2half2(__float2half_rn(oz), __float2half_rn(ow));
}

// ---------------- launch ----------------
extern "C" void kernel_launch(void* const* d_in, const int* in_sizes, int n_in,
                              void* d_out, int out_size) {
    const float* x   = (const float*)d_in[0];
    const int*   ei  = (const int*)d_in[1];
    const float* W1  = (const float*)d_in[2];
    const float* b1  = (const float*)d_in[3];
    const float* W2  = (const float*)d_in[4];
    const float* b2  = (const float*)d_in[5];
    const float* Wfc = (const float*)d_in[6];
    const float* bfc = (const float*)d_in[7];
    float*       out = (float*)d_out;

    const int* src = ei;
    const int* dst = ei + N_EDGES;

    __half *hbuf = nullptr, *abuf = nullptr, *w1 = nullptr, *w2 = nullptr, *wfc = nullptr;
    int* degp = nullptr;
    cudaGetSymbolAddress((void**)&hbuf, g_h);
    cudaGetSymbolAddress((void**)&abuf, g_a);
    cudaGetSymbolAddress((void**)&w1,   g_w1);
    cudaGetSymbolAddress((void**)&w2,   g_w2);
    cudaGetSymbolAddress((void**)&wfc,  g_wfc);
    cudaGetSymbolAddress((void**)&degp, g_deg);

    static cudaStream_t sB = nullptr;
    static cudaEvent_t  evFork = nullptr, evJoin = nullptr;
    if (!sB) {
        cudaStreamCreateWithFlags(&sB, cudaStreamNonBlocking);
        cudaEventCreateWithFlags(&evFork, cudaEventDisableTiming);
        cudaEventCreateWithFlags(&evJoin, cudaEventDisableTiming);
    }

    const int SMEM128 = (128 + 128) * ROWB;   // 69632
    const int SMEM64  = (128 + 64) * ROWB;    // 52224
    cudaFuncSetAttribute(k_gemm_mma<128, true>,  cudaFuncAttributeMaxDynamicSharedMemorySize, SMEM128);
    cudaFuncSetAttribute(k_gemm_mma<128, false>, cudaFuncAttributeMaxDynamicSharedMemorySize, SMEM128);
    cudaFuncSetAttribute(k_gemm_mma<64, false>,  cudaFuncAttributeMaxDynamicSharedMemorySize, SMEM64);

    const int nodeBlocks = (N_NODES + 255) / 256;         // 391
    const int edgeBlocks = (N_EDGES + 255) / 256;         // 6250
    const int tcBlocks   = (N_NODES + 127) / 128;         // 782
    const int aggBlocks  = (N_NODES * 32 + 255) / 256;    // 12500

    // side stream: weight prep (independent of everything)
    k_prep_w<<<64, 256, 0, sB>>>(W1, W2, Wfc);

    // main: zero degrees + histogram
    cudaMemsetAsync(degp, 0, N_NODES * sizeof(int), 0);
    k_hist<<<edgeBlocks, 256>>>(dst);

    // fork: dinv + GEMM1 on side stream, CSR tail on main
    cudaEventRecord(evFork, 0);
    cudaStreamWaitEvent(sB, evFork, 0);

    k_dinv<<<nodeBlocks, 256, 0, sB>>>();
    k_gemm_mma<128, true><<<tcBlocks, 256, SMEM128, sB>>>(x, nullptr, w1, nullptr, hbuf);
    cudaEventRecord(evJoin, sB);

    k_scan1<<<N_SCAN_BLKS, SCAN_BLK>>>();
    k_finalize<<<N_SCAN_BLKS, SCAN_BLK>>>();
    k_scatter<<<edgeBlocks, 256>>>(src, dst);

    cudaStreamWaitEvent(0, evJoin, 0);

    // serial core (agg owns the chip while it runs)
    k_agg<<<aggBlocks, 256>>>(hbuf, b1, abuf);
    k_gemm_mma<128, false><<<tcBlocks, 256, SMEM128>>>(nullptr, abuf, w2, nullptr, hbuf);
    k_agg<<<aggBlocks, 256>>>(hbuf, b2, abuf);
    k_gemm_mma<64, false><<<tcBlocks, 256, SMEM64>>>(nullptr, abuf, wfc, bfc, out);
}